// round 2
// baseline (speedup 1.0000x reference)
#include <cuda_runtime.h>
#include <math.h>

#define NN 16384
#define KK 2048
#define KP1 2049
#define MAXB 192

// ---------------- device scratch (no allocations allowed) ----------------
__device__ __align__(16) float  g_Q[(size_t)NN * KK];   // 128 MiB row-max-normalized Q~
__device__ double g_d[NN];                              // d_i = S_i^{-10}
__device__ float  g_m[NN];                              // row max of P
__device__ __align__(16) float  g_v[NN];                // v_i = a_i * d_i  (scaled a)
__device__ __align__(16) float  g_u[KK];                // b_j for j<K
__device__ float  g_blast[KP1];
__device__ double g_bK;                                 // slack b
__device__ __align__(16) float  g_zpart[MAXB * KK];
__device__ double g_apart[MAXB];
__device__ double g_errpart[MAXB];
__device__ double g_bn2part[MAXB];
__device__ unsigned int g_bar_in  = 0;
__device__ unsigned int g_bar_gen = 0;

#define INV_N (1.0/16384.0)
#define PBCOL (0.1/2048.0)      /* rho/k */
#define FI    (1.0/1.1)         /* gamma/(gamma+eps) */

// ---------------- software grid barrier (all blocks co-resident) ----------------
__device__ __forceinline__ void grid_sync(int nb) {
    __syncthreads();
    if (threadIdx.x == 0) {
        unsigned int gen = *((volatile unsigned int*)&g_bar_gen);
        __threadfence();
        unsigned int a = atomicAdd(&g_bar_in, 1u);
        if (a == (unsigned int)nb - 1u) {
            g_bar_in = 0;
            __threadfence();
            *((volatile unsigned int*)&g_bar_gen) = gen + 1u;
        } else {
            while (*((volatile unsigned int*)&g_bar_gen) == gen) { __nanosleep(64); }
        }
        __threadfence();
    }
    __syncthreads();
}

// ---------------- precompute: row max + d_i = S^-10 ----------------
__global__ void k_rowstats(const float* __restrict__ P) {
    int row = blockIdx.x;
    const float* p = P + (size_t)row * KK;
    int tid = threadIdx.x;                       // 256 threads
    __shared__ float sm[256];
    __shared__ float ss[256];

    float m = -1e30f;
    for (int j = tid; j < KK; j += 256) m = fmaxf(m, p[j]);
    sm[tid] = m; __syncthreads();
    for (int s = 128; s > 0; s >>= 1) { if (tid < s) sm[tid] = fmaxf(sm[tid], sm[tid + s]); __syncthreads(); }
    m = sm[0];

    float acc = 0.f;
    for (int j = tid; j < KK; j += 256) acc += expf(p[j] - m);
    ss[tid] = acc; __syncthreads();
    for (int s = 128; s > 0; s >>= 1) { if (tid < s) ss[tid] += ss[tid + s]; __syncthreads(); }

    if (tid == 0) {
        g_m[row] = m;
        g_d[row] = exp(-10.0 * log((double)ss[0]));   // S^-10
    }
}

// ---------------- precompute: Q~ = exp(10*(P - m_row)) ----------------
__global__ void k_fill(const float* __restrict__ P) {
    size_t total = (size_t)NN * KK / 4;
    const float4* p4 = (const float4*)P;
    float4* q4 = (float4*)g_Q;
    for (size_t i = (size_t)blockIdx.x * blockDim.x + threadIdx.x; i < total;
         i += (size_t)gridDim.x * blockDim.x) {
        int row = (int)(i >> 9);                  // (i*4)/2048
        float m = g_m[row];
        float4 v = p4[i];
        float4 r;
        r.x = expf(10.f * (v.x - m));
        r.y = expf(10.f * (v.y - m));
        r.z = expf(10.f * (v.z - m));
        r.w = expf(10.f * (v.w - m));
        q4[i] = r;
    }
}

// ---------------- init b ----------------
__global__ void k_init() {
    int t = threadIdx.x + blockIdx.x * blockDim.x;
    const float b0 = (float)(1.0 / 2049.0);
    for (int j = t; j < KK; j += blockDim.x * gridDim.x) { g_u[j] = b0; g_blast[j] = b0; }
    if (t == 0) { g_blast[KK] = b0; g_bK = 1.0 / 2049.0; }
}

// ---------------- persistent Sinkhorn loop + plan epilogue ----------------
__global__ void __launch_bounds__(1024, 1) k_main(float* __restrict__ out, int nb) {
    const int tid  = threadIdx.x;
    const int blk  = blockIdx.x;
    const int gtid = blk * 1024 + tid;
    const int nth  = nb * 1024;
    const int nwarp = nth >> 5;
    const int gw   = gtid >> 5;
    const int lane = tid & 31;

    __shared__ double s_a[32];
    __shared__ double s_e[1024];
    __shared__ double s_b2[1024];
    __shared__ int s_stop;

    const float4* Q4 = (const float4*)g_Q;
    const float4* U4 = (const float4*)g_u;

    for (int it = 0; it < 1000; ++it) {
        // ---- convergence decision (uniform across all blocks) ----
        if (tid == 0) {
            int stop = 0;
            if (it > 0) {
                double e2 = 0.0, b2 = 0.0;
                for (int p = 0; p < nb; p++) { e2 += g_errpart[p]; b2 += g_bn2part[p]; }
                if (e2 <= 1e-12 || e2 <= 1e-12 * b2) stop = 1;   // err<=1e-6 abs OR 1e-6 rel
            }
            s_stop = stop;
        }
        __syncthreads();
        if (s_stop) break;

        // ---- Phase A: y = Q~ b (warp per row), a_i, v_i = a_i*d_i ----
        double bKd  = g_bK;
        double suma = 0.0;
        for (int row = gw; row < NN; row += nwarp) {
            const float4* q = Q4 + (size_t)row * (KK / 4);
            float y = 0.f;
            #pragma unroll 4
            for (int s = 0; s < 16; s++) {
                float4 a4 = q[lane + (s << 5)];
                float4 u4 = U4[lane + (s << 5)];
                y += a4.x * u4.x; y += a4.y * u4.y;
                y += a4.z * u4.z; y += a4.w * u4.w;
            }
            #pragma unroll
            for (int off = 16; off; off >>= 1) y += __shfl_down_sync(0xffffffffu, y, off);
            if (lane == 0) {
                double d  = g_d[row];
                double qb = d * (double)y + bKd;     // (Qb)_i incl. slack
                double a  = INV_N / qb;
                suma += a;
                g_v[row] = (float)(a * d);
            }
        }
        if (lane == 0) s_a[tid >> 5] = suma;
        __syncthreads();
        if (tid == 0) { double t = 0.0; for (int w = 0; w < 32; w++) t += s_a[w]; g_apart[blk] = t; }
        grid_sync(nb);

        // ---- Phase B: z_j = sum_i Q~_ij v_i  (row panel per block, col per thread) ----
        {
            int r0 = (int)(((long long)blk * NN) / nb);
            int r1 = (int)(((long long)(blk + 1) * NN) / nb);
            float z0 = 0.f, z1 = 0.f;
            for (int i = r0; i < r1; i++) {
                float vi = g_v[i];
                const float* qr = g_Q + (size_t)i * KK;
                z0 = fmaf(qr[tid], vi, z0);
                z1 = fmaf(qr[tid + 1024], vi, z1);
            }
            g_zpart[blk * KK + tid]        = z0;
            g_zpart[blk * KK + tid + 1024] = z1;
        }
        grid_sync(nb);

        // ---- Phase C: reduce partials, b update (+^fi), err ----
        {
            double e2 = 0.0, b2 = 0.0;
            if (gtid < KP1) {
                if (gtid < KK) {
                    float z = 0.f;
                    for (int p = 0; p < nb; p++) z += g_zpart[p * KK + gtid];
                    float bn = powf((float)PBCOL / z, (float)FI);
                    double diff = (double)bn - (double)g_blast[gtid];
                    e2 = diff * diff;
                    b2 = (double)bn * (double)bn;
                    g_blast[gtid] = bn;
                    g_u[gtid]     = bn;
                } else {
                    double sa = 0.0;
                    for (int p = 0; p < nb; p++) sa += g_apart[p];
                    double bn = 0.9 / sa;                  // (1-rho)/sum(a), no ^fi on slack
                    double diff = bn - (double)g_blast[KK];
                    e2 = diff * diff; b2 = bn * bn;
                    g_blast[KK] = (float)bn;
                    g_bK = bn;
                }
            }
            s_e[tid] = e2; s_b2[tid] = b2;
            __syncthreads();
            for (int s = 512; s > 0; s >>= 1) {
                if (tid < s) { s_e[tid] += s_e[tid + s]; s_b2[tid] += s_b2[tid + s]; }
                __syncthreads();
            }
            if (tid == 0) { g_errpart[blk] = s_e[0]; g_bn2part[blk] = s_b2[0]; }
        }
        grid_sync(nb);
    }

    // ---- plan = n * a_i * Q_ij * b_j = n * v_i * Q~_ij * u_j ----
    float4* O4 = (float4*)out;
    for (int row = gw; row < NN; row += nwarp) {
        float nf = (float)(16384.0 * (double)g_v[row]);
        const float4* q = Q4 + (size_t)row * (KK / 4);
        float4* o = O4 + (size_t)row * (KK / 4);
        #pragma unroll 4
        for (int s = 0; s < 16; s++) {
            float4 a4 = q[lane + (s << 5)];
            float4 u4 = U4[lane + (s << 5)];
            float4 r;
            r.x = nf * a4.x * u4.x;
            r.y = nf * a4.y * u4.y;
            r.z = nf * a4.z * u4.z;
            r.w = nf * a4.w * u4.w;
            o[lane + (s << 5)] = r;
        }
    }
}

// ---------------- launch ----------------
extern "C" void kernel_launch(void* const* d_in, const int* in_sizes, int n_in,
                              void* d_out, int out_size) {
    const float* P = (const float*)d_in[0];
    float* out = (float*)d_out;

    int dev = 0; cudaGetDevice(&dev);
    int nsm = 0; cudaDeviceGetAttribute(&nsm, cudaDevAttrMultiProcessorCount, dev);
    if (nsm < 1)  nsm = 148;
    if (nsm > MAXB) nsm = MAXB;

    k_rowstats<<<NN, 256>>>(P);
    k_fill<<<nsm * 8, 256>>>(P);
    k_init<<<4, 512>>>();
    k_main<<<nsm, 1024>>>(out, nsm);
}

// round 7
// speedup vs baseline: 1.5525x; 1.5525x over previous
#include <cuda_runtime.h>
#include <math.h>

#define NN 16384
#define KK 2048
#define MAXB 192
#define NITER 1000

// ---------------- device scratch (no allocations allowed) ----------------
__device__ __align__(256) float g_Q[(size_t)NN * KK];   // 128 MiB row-max-normalized Q~
__device__ double g_d[NN];                              // d_i = S_i^{-10}
__device__ float  g_m[NN];                              // row max of P
__device__ __align__(16) float  g_v[NN];                // v_i = a_i * d_i
__device__ __align__(16) float  g_u[KK];                // b_j for j<K
__device__ double g_bK;                                 // slack b
__device__ __align__(16) float  g_zpart[MAXB * KK];
__device__ double g_apart[MAXB];
__device__ unsigned int g_bar_in  = 0;
__device__ unsigned int g_bar_gen = 0;

#define INV_N   (1.0/16384.0)
#define PBCOL_F (4.8828125e-05f)   /* rho/k = 0.1/2048 */
#define FI_F    (0.909090936f)     /* gamma/(gamma+eps) = 1/1.1 */

// ---------------- software grid barrier (all blocks co-resident; proven in R2) ----------------
__device__ __forceinline__ void grid_sync(int nb) {
    __syncthreads();
    if (threadIdx.x == 0) {
        unsigned int gen = *((volatile unsigned int*)&g_bar_gen);
        __threadfence();
        unsigned int a = atomicAdd(&g_bar_in, 1u);
        if (a == (unsigned int)nb - 1u) {
            g_bar_in = 0;
            __threadfence();
            *((volatile unsigned int*)&g_bar_gen) = gen + 1u;
        } else {
            while (*((volatile unsigned int*)&g_bar_gen) == gen) { __nanosleep(64); }
        }
        __threadfence();
    }
    __syncthreads();
}

// ---------------- precompute: row max + d_i = S^-10 ----------------
__global__ void k_rowstats(const float* __restrict__ P) {
    int row = blockIdx.x;
    const float* p = P + (size_t)row * KK;
    int tid = threadIdx.x;                       // 256 threads
    __shared__ float sm[256];
    __shared__ float ss[256];

    float m = -1e30f;
    for (int j = tid; j < KK; j += 256) m = fmaxf(m, p[j]);
    sm[tid] = m; __syncthreads();
    for (int s = 128; s > 0; s >>= 1) { if (tid < s) sm[tid] = fmaxf(sm[tid], sm[tid + s]); __syncthreads(); }
    m = sm[0];

    float acc = 0.f;
    for (int j = tid; j < KK; j += 256) acc += expf(p[j] - m);
    ss[tid] = acc; __syncthreads();
    for (int s = 128; s > 0; s >>= 1) { if (tid < s) ss[tid] += ss[tid + s]; __syncthreads(); }

    if (tid == 0) {
        g_m[row] = m;
        g_d[row] = exp(-10.0 * log((double)ss[0]));   // S^-10
    }
}

// ---------------- precompute: Q~ = exp(10*(P - m_row)) ----------------
__global__ void k_fill(const float* __restrict__ P) {
    size_t total = (size_t)NN * KK / 4;
    const float4* p4 = (const float4*)P;
    float4* q4 = (float4*)g_Q;
    for (size_t i = (size_t)blockIdx.x * blockDim.x + threadIdx.x; i < total;
         i += (size_t)gridDim.x * blockDim.x) {
        int row = (int)(i >> 9);
        float m = g_m[row];
        float4 v = p4[i];
        float4 r;
        r.x = expf(10.f * (v.x - m));
        r.y = expf(10.f * (v.y - m));
        r.z = expf(10.f * (v.z - m));
        r.w = expf(10.f * (v.w - m));
        q4[i] = r;
    }
}

// ---------------- init b ----------------
__global__ void k_init() {
    int t = threadIdx.x + blockIdx.x * blockDim.x;
    const float b0 = (float)(1.0 / 2049.0);
    for (int j = t; j < KK; j += blockDim.x * gridDim.x) g_u[j] = b0;
    if (t == 0) g_bK = 1.0 / 2049.0;
}

// ---------------- persistent Sinkhorn loop (fixed 1000 iters) + plan ----------------
__global__ void __launch_bounds__(1024, 1) k_main(float* __restrict__ out, int nb) {
    const int tid  = threadIdx.x;
    const int blk  = blockIdx.x;
    const int w    = tid >> 5;
    const int lane = tid & 31;

    __shared__ __align__(16) float su[KK];   // current b (real cols)
    __shared__ float  sv[32];                // v for current chunk rows
    __shared__ double sa[32];                // per-warp a partial sums

    const int r0 = (int)(((long long)blk       * NN) / nb);
    const int r1 = (int)(((long long)(blk + 1) * NN) / nb);

    for (int it = 0; it < NITER; ++it) {
        // stage current u into smem
        for (int j = tid; j < KK; j += 1024) su[j] = g_u[j];
        __syncthreads();

        const double bK = g_bK;
        const float4* su4 = (const float4*)su;
        double suma = 0.0;
        float z0 = 0.f, z1 = 0.f;

        for (int c0 = r0; c0 < r1; c0 += 32) {
            const int nr = min(32, r1 - c0);

            // ---- pass1: warp per row, 2x float4 per lane per step: y = q . u ----
            if (w < nr) {
                const int row = c0 + w;
                const float4* q4 = (const float4*)(g_Q + (size_t)row * KK);
                float y0 = 0.f, y1 = 0.f, y2 = 0.f, y3 = 0.f;
                #pragma unroll
                for (int s = 0; s < 8; s++) {
                    const int j4 = (s << 6) + (lane << 1);     // float4 index
                    float4 lo = __ldg(q4 + j4);
                    float4 hi = __ldg(q4 + j4 + 1);
                    float4 b0 = su4[j4];
                    float4 b1 = su4[j4 + 1];
                    y0 = fmaf(lo.x, b0.x, fmaf(lo.y, b0.y, y0));
                    y1 = fmaf(lo.z, b0.z, fmaf(lo.w, b0.w, y1));
                    y2 = fmaf(hi.x, b1.x, fmaf(hi.y, b1.y, y2));
                    y3 = fmaf(hi.z, b1.z, fmaf(hi.w, b1.w, y3));
                }
                float y = (y0 + y1) + (y2 + y3);
                #pragma unroll
                for (int off = 16; off; off >>= 1) y += __shfl_xor_sync(0xffffffffu, y, off);
                if (lane == 0) {
                    double d = g_d[row];
                    double a = INV_N / (d * (double)y + bK);
                    suma += a;
                    float vf = (float)(a * d);
                    sv[w]    = vf;
                    g_v[row] = vf;
                }
            }
            __syncthreads();

            // ---- pass2: z_j += v_i * q_ij over chunk (rows hot in L1/L2) ----
            {
                const float* qb = g_Q + (size_t)c0 * KK;
                #pragma unroll 4
                for (int r = 0; r < nr; r++) {
                    float vr = sv[r];
                    const float* qr = qb + (size_t)r * KK;
                    z0 = fmaf(qr[tid],        vr, z0);
                    z1 = fmaf(qr[tid + 1024], vr, z1);
                }
            }
            __syncthreads();
        }

        // ---- publish partials ----
        g_zpart[blk * KK + tid]        = z0;
        g_zpart[blk * KK + tid + 1024] = z1;
        if (lane == 0) sa[w] = suma;
        __syncthreads();
        if (tid == 0) {
            double t = 0.0;
            #pragma unroll
            for (int q = 0; q < 32; q++) t += sa[q];
            g_apart[blk] = t;
        }
        grid_sync(nb);

        // ---- b update: block-strided column ownership (valid for any nb >= 67) ----
        {
            int col = blk + nb * w;                  // w in 0..31
            if (col < KK) {
                float s = 0.f;
                for (int p = lane; p < nb; p += 32) s += g_zpart[p * KK + col];
                #pragma unroll
                for (int off = 16; off; off >>= 1) s += __shfl_xor_sync(0xffffffffu, s, off);
                if (lane == 0) g_u[col] = powf(PBCOL_F / s, FI_F);
            }
            if (blk == 0 && w == 31) {               // slack (slot 31*nb >= KK for nb >= 67)
                double s = 0.0;
                for (int p = lane; p < nb; p += 32) s += g_apart[p];
                #pragma unroll
                for (int off = 16; off; off >>= 1) s += __shfl_xor_sync(0xffffffffu, s, off);
                if (lane == 0) g_bK = 0.9 / s;
            }
        }
        grid_sync(nb);
    }

    // ---- plan = n * v_i * Q~_ij * u_j ----
    {
        const int nwarp = nb * 32;
        const int gw = blk * 32 + w;
        const float4* Q4 = (const float4*)g_Q;
        const float4* U4 = (const float4*)g_u;
        float4* O4 = (float4*)out;
        for (int row = gw; row < NN; row += nwarp) {
            float nf = (float)(16384.0 * (double)g_v[row]);
            const float4* q = Q4 + (size_t)row * (KK / 4);
            float4* o = O4 + (size_t)row * (KK / 4);
            #pragma unroll 4
            for (int s = 0; s < 16; s++) {
                float4 a4 = __ldg(q + lane + (s << 5));
                float4 u4 = __ldg(U4 + lane + (s << 5));
                float4 r;
                r.x = nf * a4.x * u4.x;
                r.y = nf * a4.y * u4.y;
                r.z = nf * a4.z * u4.z;
                r.w = nf * a4.w * u4.w;
                o[lane + (s << 5)] = r;
            }
        }
    }
}

// ---------------- launch ----------------
extern "C" void kernel_launch(void* const* d_in, const int* in_sizes, int n_in,
                              void* d_out, int out_size) {
    const float* P = (const float*)d_in[0];
    float* out = (float*)d_out;

    int dev = 0; cudaGetDevice(&dev);
    int nsm = 0; cudaDeviceGetAttribute(&nsm, cudaDevAttrMultiProcessorCount, dev);
    if (nsm < 1)    nsm = 148;
    if (nsm > MAXB) nsm = MAXB;   // scratch bound; slack mapping needs nb >= 67 (any real part qualifies)

    k_rowstats<<<NN, 256>>>(P);
    k_fill<<<nsm * 8, 256>>>(P);
    k_init<<<4, 512>>>();
    k_main<<<nsm, 1024>>>(out, nsm);
}

// round 8
// speedup vs baseline: 1.8757x; 1.2082x over previous
#include <cuda_runtime.h>
#include <math.h>

#define NN 16384
#define KK 2048
#define MAXB 192
#define NITER 1000
#define TPB 512                 /* 16 warps, <=128 regs/thread */
#define WPB 16

// dynamic smem: su[2048] + zones[8][2048] floats = 72 KB
#define SMEM_BYTES ((KK + 8 * KK) * 4)

// ---------------- device scratch (no allocations allowed) ----------------
__device__ __align__(256) float g_Q[(size_t)NN * KK];   // 128 MiB row-max-normalized Q~
__device__ double g_d[NN];                              // d_i = S_i^{-10}
__device__ float  g_m[NN];                              // row max of P
__device__ __align__(16) float  g_v[NN];                // v_i = a_i * d_i
__device__ __align__(16) float  g_u[KK];                // b_j for j<K
__device__ double g_bK;                                 // slack b
__device__ __align__(16) float  g_zpart[MAXB * KK];
__device__ double g_apart[MAXB];
__device__ unsigned int g_bar_in  = 0;
__device__ unsigned int g_bar_gen = 0;

#define INV_N   (1.0/16384.0)
#define PBCOL_F (4.8828125e-05f)   /* rho/k = 0.1/2048 */
#define FI_F    (0.909090936f)     /* gamma/(gamma+eps) = 1/1.1 */

// ---------------- software grid barrier (all blocks co-resident; proven R2/R7) ----------------
__device__ __forceinline__ void grid_sync(int nb) {
    __syncthreads();
    if (threadIdx.x == 0) {
        unsigned int gen = *((volatile unsigned int*)&g_bar_gen);
        __threadfence();
        unsigned int a = atomicAdd(&g_bar_in, 1u);
        if (a == (unsigned int)nb - 1u) {
            g_bar_in = 0;
            __threadfence();
            *((volatile unsigned int*)&g_bar_gen) = gen + 1u;
        } else {
            while (*((volatile unsigned int*)&g_bar_gen) == gen) { __nanosleep(64); }
        }
        __threadfence();
    }
    __syncthreads();
}

// ---------------- precompute: row max + d_i = S^-10 ----------------
__global__ void k_rowstats(const float* __restrict__ P) {
    int row = blockIdx.x;
    const float* p = P + (size_t)row * KK;
    int tid = threadIdx.x;                       // 256 threads
    __shared__ float sm[256];
    __shared__ float ss[256];

    float m = -1e30f;
    for (int j = tid; j < KK; j += 256) m = fmaxf(m, p[j]);
    sm[tid] = m; __syncthreads();
    for (int s = 128; s > 0; s >>= 1) { if (tid < s) sm[tid] = fmaxf(sm[tid], sm[tid + s]); __syncthreads(); }
    m = sm[0];

    float acc = 0.f;
    for (int j = tid; j < KK; j += 256) acc += expf(p[j] - m);
    ss[tid] = acc; __syncthreads();
    for (int s = 128; s > 0; s >>= 1) { if (tid < s) ss[tid] += ss[tid + s]; __syncthreads(); }

    if (tid == 0) {
        g_m[row] = m;
        g_d[row] = exp(-10.0 * log((double)ss[0]));   // S^-10
    }
}

// ---------------- precompute: Q~ = exp(10*(P - m_row)) ----------------
__global__ void k_fill(const float* __restrict__ P) {
    size_t total = (size_t)NN * KK / 4;
    const float4* p4 = (const float4*)P;
    float4* q4 = (float4*)g_Q;
    for (size_t i = (size_t)blockIdx.x * blockDim.x + threadIdx.x; i < total;
         i += (size_t)gridDim.x * blockDim.x) {
        int row = (int)(i >> 9);
        float m = g_m[row];
        float4 v = p4[i];
        float4 r;
        r.x = expf(10.f * (v.x - m));
        r.y = expf(10.f * (v.y - m));
        r.z = expf(10.f * (v.z - m));
        r.w = expf(10.f * (v.w - m));
        q4[i] = r;
    }
}

// ---------------- init b ----------------
__global__ void k_init() {
    int t = threadIdx.x + blockIdx.x * blockDim.x;
    const float b0 = (float)(1.0 / 2049.0);
    for (int j = t; j < KK; j += blockDim.x * gridDim.x) g_u[j] = b0;
    if (t == 0) g_bK = 1.0 / 2049.0;
}

// ---------------- persistent Sinkhorn loop (fixed 1000 iters) + plan ----------------
__global__ void __launch_bounds__(TPB, 1) k_main(float* __restrict__ out, int nb) {
    const int tid  = threadIdx.x;
    const int blk  = blockIdx.x;
    const int w    = tid >> 5;
    const int lane = tid & 31;

    extern __shared__ __align__(16) float smem_dyn[];
    float*  su     = smem_dyn;               // [KK]
    float4* zones4 = (float4*)(smem_dyn + KK); // [8][KK/4]
    __shared__ double sa[WPB];

    float4* su4 = (float4*)su;

    const int r0 = (int)(((long long)blk       * NN) / nb);
    const int r1 = (int)(((long long)(blk + 1) * NN) / nb);

    for (int it = 0; it < NITER; ++it) {
        // stage current u into smem
        for (int j = tid; j < KK; j += TPB) su[j] = g_u[j];
        __syncthreads();

        const double bK = g_bK;
        double suma = 0.0;

        float4 z4[16];
        #pragma unroll
        for (int s = 0; s < 16; s++) z4[s] = make_float4(0.f, 0.f, 0.f, 0.f);

        // ---- fully independent warps: per-row dot -> v -> immediate rank-1 accumulate ----
        for (int row = r0 + w; row < r1; row += WPB) {
            const float4* q4 = (const float4*)(g_Q + (size_t)row * KK);

            float y0 = 0.f, y1 = 0.f, y2 = 0.f, y3 = 0.f;
            #pragma unroll
            for (int s = 0; s < 16; s += 4) {
                float4 a0 = __ldg(q4 + ((s + 0) << 5) + lane);
                float4 a1 = __ldg(q4 + ((s + 1) << 5) + lane);
                float4 a2 = __ldg(q4 + ((s + 2) << 5) + lane);
                float4 a3 = __ldg(q4 + ((s + 3) << 5) + lane);
                float4 b0 = su4[((s + 0) << 5) + lane];
                float4 b1 = su4[((s + 1) << 5) + lane];
                float4 b2 = su4[((s + 2) << 5) + lane];
                float4 b3 = su4[((s + 3) << 5) + lane];
                y0 = fmaf(a0.x, b0.x, fmaf(a0.y, b0.y, fmaf(a0.z, b0.z, fmaf(a0.w, b0.w, y0))));
                y1 = fmaf(a1.x, b1.x, fmaf(a1.y, b1.y, fmaf(a1.z, b1.z, fmaf(a1.w, b1.w, y1))));
                y2 = fmaf(a2.x, b2.x, fmaf(a2.y, b2.y, fmaf(a2.z, b2.z, fmaf(a2.w, b2.w, y2))));
                y3 = fmaf(a3.x, b3.x, fmaf(a3.y, b3.y, fmaf(a3.z, b3.z, fmaf(a3.w, b3.w, y3))));
            }
            float y = (y0 + y1) + (y2 + y3);
            #pragma unroll
            for (int off = 16; off; off >>= 1) y += __shfl_xor_sync(0xffffffffu, y, off);

            // every lane computes v redundantly (fp64, trivial cost; no broadcast needed)
            double d = g_d[row];
            double a = INV_N / (d * (double)y + bK);
            float vf = (float)(a * d);
            if (lane == 0) { suma += a; g_v[row] = vf; }

            // re-read row (L1/L2 hot) and accumulate z
            #pragma unroll
            for (int s = 0; s < 16; s++) {
                float4 q = __ldg(q4 + (s << 5) + lane);
                z4[s].x = fmaf(q.x, vf, z4[s].x);
                z4[s].y = fmaf(q.y, vf, z4[s].y);
                z4[s].z = fmaf(q.z, vf, z4[s].z);
                z4[s].w = fmaf(q.w, vf, z4[s].w);
            }
        }
        if (lane == 0) sa[w] = suma;

        // ---- z tree-reduce: 16 warps -> 8 zones -> gather ----
        __syncthreads();
        if (w >= 8) {
            float4* zn = zones4 + (size_t)(w - 8) * (KK / 4);
            #pragma unroll
            for (int s = 0; s < 16; s++) zn[(s << 5) + lane] = z4[s];
        }
        __syncthreads();
        if (w < 8) {
            float4* zn = zones4 + (size_t)w * (KK / 4);
            #pragma unroll
            for (int s = 0; s < 16; s++) {
                float4 t = zn[(s << 5) + lane];
                t.x += z4[s].x; t.y += z4[s].y; t.z += z4[s].z; t.w += z4[s].w;
                zn[(s << 5) + lane] = t;
            }
        }
        __syncthreads();
        {
            float4 acc = zones4[tid];
            #pragma unroll
            for (int z = 1; z < 8; z++) {
                float4 t = zones4[(size_t)z * (KK / 4) + tid];
                acc.x += t.x; acc.y += t.y; acc.z += t.z; acc.w += t.w;
            }
            ((float4*)(g_zpart + (size_t)blk * KK))[tid] = acc;
        }
        if (tid == 0) {
            double t = 0.0;
            #pragma unroll
            for (int q = 0; q < WPB; q++) t += sa[q];
            g_apart[blk] = t;
        }
        grid_sync(nb);

        // ---- b update: block-strided column ownership (needs 15*nb >= KK, i.e. nb >= 137) ----
        {
            int col = blk + nb * w;                  // w in 0..15
            if (col < KK) {
                float s = 0.f;
                for (int p = lane; p < nb; p += 32) s += g_zpart[p * KK + col];
                #pragma unroll
                for (int off = 16; off; off >>= 1) s += __shfl_xor_sync(0xffffffffu, s, off);
                if (lane == 0) g_u[col] = powf(PBCOL_F / s, FI_F);
            }
            if (blk == 0 && w == WPB - 1 && 15 * nb >= KK) {   // slack owner (slot unused)
                double s = 0.0;
                for (int p = lane; p < nb; p += 32) s += g_apart[p];
                #pragma unroll
                for (int off = 16; off; off >>= 1) s += __shfl_xor_sync(0xffffffffu, s, off);
                if (lane == 0) g_bK = 0.9 / s;
            }
        }
        grid_sync(nb);
    }

    // ---- plan = n * v_i * Q~_ij * u_j ----
    {
        const int nwarp = nb * WPB;
        const int gw = blk * WPB + w;
        const float4* Q4 = (const float4*)g_Q;
        const float4* U4 = (const float4*)g_u;
        float4* O4 = (float4*)out;
        for (int row = gw; row < NN; row += nwarp) {
            float nf = (float)(16384.0 * (double)g_v[row]);
            const float4* q = Q4 + (size_t)row * (KK / 4);
            float4* o = O4 + (size_t)row * (KK / 4);
            #pragma unroll 4
            for (int s = 0; s < 16; s++) {
                float4 a4 = __ldg(q + (s << 5) + lane);
                float4 u4 = __ldg(U4 + (s << 5) + lane);
                float4 r;
                r.x = nf * a4.x * u4.x;
                r.y = nf * a4.y * u4.y;
                r.z = nf * a4.z * u4.z;
                r.w = nf * a4.w * u4.w;
                o[(s << 5) + lane] = r;
            }
        }
    }
}

// ---------------- launch ----------------
extern "C" void kernel_launch(void* const* d_in, const int* in_sizes, int n_in,
                              void* d_out, int out_size) {
    const float* P = (const float*)d_in[0];
    float* out = (float*)d_out;

    int dev = 0; cudaGetDevice(&dev);
    int nsm = 0; cudaDeviceGetAttribute(&nsm, cudaDevAttrMultiProcessorCount, dev);
    if (nsm < 1)    nsm = 148;
    if (nsm > MAXB) nsm = MAXB;   // b-update mapping needs nb >= 137 (any real part: 148+)

    cudaFuncSetAttribute(k_main, cudaFuncAttributeMaxDynamicSharedMemorySize, SMEM_BYTES);

    k_rowstats<<<NN, 256>>>(P);
    k_fill<<<nsm * 8, 256>>>(P);
    k_init<<<4, 512>>>();
    k_main<<<nsm, TPB, SMEM_BYTES>>>(out, nsm);
}